// round 6
// baseline (speedup 1.0000x reference)
#include <cuda_runtime.h>

#define ROWS 8
#define THREADS 512
#define D 4096
#define NCHUNK 64
#define CHUNK_BYTES 32768
#define CHUNK_FLOATS 8192
#define XOFF 256                        /* floats: x tile at byte 1024   */
#define CBOFF (XOFF + ROWS * D)         /* floats: C ring at byte 132096 */
#define CBOFF_BYTES (CBOFF * 4)
#define SMEM_TOTAL (CBOFF_BYTES + 3 * CHUNK_BYTES)   /* 230400 bytes */

typedef unsigned long long u64;
typedef unsigned int u32;

// H-folded, pre-scaled, TRANSPOSED inner matrices: g_C[s][i][n][o] = ((B[s][n] @ H64)/64)[i][o]
__device__ float g_C[2 * 64 * 64 * 64];

__device__ __forceinline__ u64 pack2(float x) {
    u64 r; asm("mov.b64 %0,{%1,%1};" : "=l"(r) : "f"(x)); return r;
}
__device__ __forceinline__ void fma2(u64& d, u64 a, u64 b) {
    asm("fma.rn.f32x2 %0,%1,%2,%3;" : "=l"(d) : "l"(a), "l"(b), "l"(d));
}
__device__ __forceinline__ int swz(int n, int c) {
    return n * 64 + (c ^ ((n & 7) << 3));
}
__device__ __forceinline__ u32 s2u(const void* p) {
    u32 a; asm("{ .reg .u64 t; cvta.to.shared.u64 t, %1; cvt.u32.u64 %0, t; }" : "=r"(a) : "l"(p));
    return a;
}
__device__ __forceinline__ void mbar_init(u32 a, u32 cnt) {
    asm volatile("mbarrier.init.shared.b64 [%0], %1;" :: "r"(a), "r"(cnt) : "memory");
}
__device__ __forceinline__ void mbar_arrive(u32 a) {
    asm volatile("mbarrier.arrive.release.cta.shared::cta.b64 _, [%0];" :: "r"(a) : "memory");
}
__device__ __forceinline__ void mbar_expect_tx(u32 a, u32 b) {
    asm volatile("mbarrier.arrive.expect_tx.shared.b64 _, [%0], %1;" :: "r"(a), "r"(b) : "memory");
}
__device__ __forceinline__ void mbar_wait(u32 a, u32 parity) {
    asm volatile(
        "{\n\t.reg .pred P;\n\t"
        "W%=:\n\t"
        "mbarrier.try_wait.parity.acquire.cta.shared::cta.b64 P, [%0], %1, 0x989680;\n\t"
        "@P bra.uni E%=;\n\t"
        "bra.uni W%=;\n\t"
        "E%=:\n\t}"
        :: "r"(a), "r"(parity) : "memory");
}
__device__ __forceinline__ void bulk_g2s(u32 dst, const void* src, u32 bytes, u32 mbar) {
    asm volatile(
        "cp.async.bulk.shared::cluster.global.mbarrier::complete_tx::bytes [%0], [%1], %2, [%3];"
        :: "r"(dst), "l"(src), "r"(bytes), "r"(mbar) : "memory");
}

// ---------------- prepass: C_t[s][i][n][o] = fwht64(B[s][n][i][:]) / 64 ----------------
__global__ void prep_kernel(const float* __restrict__ innerB) {
    const int t = blockIdx.x * blockDim.x + threadIdx.x;   // (s*64+n)*64+i
    const int s = t >> 12;
    const int n = (t >> 6) & 63;
    const int i = t & 63;
    const float4* src = reinterpret_cast<const float4*>(innerB + (size_t)t * 64);
    float v[64];
    #pragma unroll
    for (int k = 0; k < 16; k++) {
        float4 f = src[k];
        v[4*k] = f.x; v[4*k+1] = f.y; v[4*k+2] = f.z; v[4*k+3] = f.w;
    }
    #pragma unroll
    for (int h = 1; h < 64; h <<= 1)
        #pragma unroll
        for (int m = 0; m < 64; m += 2*h)
            #pragma unroll
            for (int k = 0; k < h; k++) {
                float a = v[m+k], b = v[m+k+h];
                v[m+k] = a + b; v[m+k+h] = a - b;
            }
    float4* dst = reinterpret_cast<float4*>(g_C + (((size_t)(s * 64 + i) * 64 + n) * 64));
    const float sc = 1.0f / 64.0f;
    #pragma unroll
    for (int k = 0; k < 16; k++)
        dst[k] = make_float4(v[4*k]*sc, v[4*k+1]*sc, v[4*k+2]*sc, v[4*k+3]*sc);
}

// ---------------- main fused kernel ----------------
__global__ __launch_bounds__(THREADS, 1)
void bh_fused_kernel(const float* __restrict__ x,
                     const float* __restrict__ finalB,
                     float* __restrict__ out)
{
    extern __shared__ float sm[];
    float* sd  = sm + XOFF;          // x tile (swizzled)
    float* cbf = sm + CBOFF;         // C ring buffer (3 slots)
    const u32 sbase = s2u(sm);
    const int tid  = threadIdx.x;
    const int lane = tid & 31;
    const int wid  = tid >> 5;
    const size_t row0 = (size_t)blockIdx.x * ROWS;

    if (tid == 0) {
        #pragma unroll
        for (int s = 0; s < 3; s++) {
            mbar_init(sbase + s * 8, 1);             // full[s]
            mbar_init(sbase + 32 + s * 8, THREADS);  // empty[s]
        }
    }

    // ---- load ROWS rows (coalesced gmem read, swizzled smem store) ----
    {
        const float4* gx = reinterpret_cast<const float4*>(x + row0 * D);
        float4* s4 = reinterpret_cast<float4*>(sd);
        #pragma unroll
        for (int k = 0; k < (ROWS * D / 4) / THREADS; k++) {
            const int f  = tid + k * THREADS;
            const int r  = f >> 10;
            const int cq = f & 1023;
            const int n  = cq >> 4;
            const int c  = (cq & 15) * 4;
            s4[r * 1024 + (swz(n, c) >> 2)] = gx[f];
        }
    }
    __syncthreads();     // also publishes mbarrier inits

    // prologue: warps 0..2 issue chunks 0..2
    if (wid < 3 && lane == 0) {
        mbar_expect_tx(sbase + wid * 8, CHUNK_BYTES);
        bulk_g2s(sbase + CBOFF_BYTES + wid * CHUNK_BYTES,
                 g_C + (size_t)wid * CHUNK_FLOATS, CHUNK_BYTES, sbase + wid * 8);
    }

    const int g  = tid >> 3;         // group 0..63
    const int ob = (tid & 7) * 8;    // output-col base
    const int pb = swz(g, ob);

    u64 acc[ROWS][4];

    #pragma unroll 1
    for (int c = 0; c < NCHUNK; c++) {
        if ((c & 31) == 0) {
            #pragma unroll
            for (int r = 0; r < ROWS; r++)
                #pragma unroll
                for (int p = 0; p < 4; p++)
                    acc[r][p] = 0ull;
        }
        const int slot  = c % 3;
        const int phase = (c / 3) & 1;
        mbar_wait(sbase + slot * 8, phase);

        const float* Cs = cbf + slot * CHUNK_FLOATS + g * 64 + ob;
        const ulonglong2 a01 = *reinterpret_cast<const ulonglong2*>(Cs);
        const ulonglong2 a23 = *reinterpret_cast<const ulonglong2*>(Cs + 4);
        const ulonglong2 d01 = *reinterpret_cast<const ulonglong2*>(Cs + 4096);
        const ulonglong2 d23 = *reinterpret_cast<const ulonglong2*>(Cs + 4100);

        const int j0 = (c & 31) * 2;
        const int pj = swz(g, j0);
        #pragma unroll
        for (int r = 0; r < ROWS; r++) {
            const float2 xp = *reinterpret_cast<const float2*>(&sd[r * D + pj]);
            const u64 x0 = pack2(xp.x);
            const u64 x1 = pack2(xp.y);
            fma2(acc[r][0], x0, a01.x);
            fma2(acc[r][1], x0, a01.y);
            fma2(acc[r][2], x0, a23.x);
            fma2(acc[r][3], x0, a23.y);
            fma2(acc[r][0], x1, d01.x);
            fma2(acc[r][1], x1, d01.y);
            fma2(acc[r][2], x1, d23.x);
            fma2(acc[r][3], x1, d23.y);
        }
        mbar_arrive(sbase + 32 + slot * 8);   // done reading this slot

        const int cn = c + 3;                 // (c+3)%3 == slot
        if (cn < NCHUNK && wid == (cn & 15) && lane == 0) {
            mbar_wait(sbase + 32 + slot * 8, phase);   // all consumed chunk c
            mbar_expect_tx(sbase + slot * 8, CHUNK_BYTES);
            bulk_g2s(sbase + CBOFF_BYTES + slot * CHUNK_BYTES,
                     g_C + (size_t)cn * CHUNK_FLOATS, CHUNK_BYTES, sbase + slot * 8);
        }

        if ((c & 31) == 31) {   // end of a stage: writeback + outer H64
            __syncthreads();
            #pragma unroll
            for (int r = 0; r < ROWS; r++) {
                ulonglong2* sp = reinterpret_cast<ulonglong2*>(&sd[r * D + pb]);
                sp[0] = make_ulonglong2(acc[r][0], acc[r][1]);
                sp[1] = make_ulonglong2(acc[r][2], acc[r][3]);
            }
            __syncthreads();
            {
                const int hr = tid >> 6;
                const int hj = tid & 63;
                float v[64];
                #pragma unroll
                for (int m = 0; m < 64; m++)
                    v[m] = sd[hr * D + m * 64 + (hj ^ ((m & 7) << 3))];
                #pragma unroll
                for (int h = 1; h < 64; h <<= 1)
                    #pragma unroll
                    for (int m0 = 0; m0 < 64; m0 += 2*h)
                        #pragma unroll
                        for (int k = 0; k < h; k++) {
                            float a = v[m0+k], b = v[m0+k+h];
                            v[m0+k] = a + b; v[m0+k+h] = a - b;
                        }
                #pragma unroll
                for (int m = 0; m < 64; m++)
                    sd[hr * D + m * 64 + (hj ^ ((m & 7) << 3))] = v[m];
            }
            __syncthreads();
        }
    }

    // ---------------- final block-diag 128 x (32x32) matmul -> GMEM ----------------
    {
        const int rect = tid >> 2;        // 0..127 (4 threads per rect)
        const int ob2  = (tid & 3) * 8;
        const int n    = rect >> 1;
        const int cb   = (rect & 1) * 32;
        const float* B = finalB + (size_t)rect * 32 * 32;

        u64 facc[ROWS][4];
        #pragma unroll
        for (int r = 0; r < ROWS; r++)
            #pragma unroll
            for (int p = 0; p < 4; p++)
                facc[r][p] = 0ull;

        #pragma unroll 2
        for (int j = 0; j < 32; j += 4) {
            const int pj = swz(n, cb + j);
            float4 xv[ROWS];
            #pragma unroll
            for (int r = 0; r < ROWS; r++)
                xv[r] = *reinterpret_cast<const float4*>(&sd[r * D + pj]);
            #pragma unroll
            for (int jj = 0; jj < 4; jj++) {
                const ulonglong2 b01 = *reinterpret_cast<const ulonglong2*>(&B[(j + jj) * 32 + ob2]);
                const ulonglong2 b23 = *reinterpret_cast<const ulonglong2*>(&B[(j + jj) * 32 + ob2 + 4]);
                #pragma unroll
                for (int r = 0; r < ROWS; r++) {
                    const float xs = (jj == 0) ? xv[r].x : (jj == 1) ? xv[r].y
                                   : (jj == 2) ? xv[r].z : xv[r].w;
                    const u64 xs2 = pack2(xs);
                    fma2(facc[r][0], xs2, b01.x);
                    fma2(facc[r][1], xs2, b01.y);
                    fma2(facc[r][2], xs2, b23.x);
                    fma2(facc[r][3], xs2, b23.y);
                }
            }
        }
        #pragma unroll
        for (int r = 0; r < ROWS; r++) {
            ulonglong2* op = reinterpret_cast<ulonglong2*>(out + (row0 + r) * D + rect * 32 + ob2);
            op[0] = make_ulonglong2(facc[r][0], facc[r][1]);
            op[1] = make_ulonglong2(facc[r][2], facc[r][3]);
        }
    }
}

extern "C" void kernel_launch(void* const* d_in, const int* in_sizes, int n_in,
                              void* d_out, int out_size) {
    const float* x  = (const float*)d_in[0];   // [4,4096,4096] f32
    const float* iB = (const float*)d_in[1];   // [2,64,64,64]  f32
    const float* fB = (const float*)d_in[2];   // [128,32,32]   f32
    float* out = (float*)d_out;                // [4,4096,4096] f32

    prep_kernel<<<64, 128>>>(iB);

    cudaFuncSetAttribute(bh_fused_kernel,
                         cudaFuncAttributeMaxDynamicSharedMemorySize, SMEM_TOTAL);
    const int nrows = 4 * 4096;
    bh_fused_kernel<<<nrows / ROWS, THREADS, SMEM_TOTAL>>>(x, fB, out);
}

// round 7
// speedup vs baseline: 1.7496x; 1.7496x over previous
#include <cuda_runtime.h>

#define ROWS 8
#define THREADS 512
#define D 4096

typedef unsigned long long u64;

// H-folded, pre-scaled inner matrices: C[s][n] = (B[s][n] @ H64) / 64
__device__ float g_C[2 * 64 * 64 * 64];

__device__ __forceinline__ u64 pack2(float x) {
    u64 r; asm("mov.b64 %0,{%1,%1};" : "=l"(r) : "f"(x)); return r;
}
__device__ __forceinline__ void fma2(u64& d, u64 a, u64 b) {
    asm("fma.rn.f32x2 %0,%1,%2,%3;" : "=l"(d) : "l"(a), "l"(b), "l"(d));
}
__device__ __forceinline__ u64 add2(u64 a, u64 b) {
    u64 r; asm("add.rn.f32x2 %0,%1,%2;" : "=l"(r) : "l"(a), "l"(b)); return r;
}
// a - b  ==  fma(b, -1, a)
__device__ __forceinline__ u64 sub2(u64 a, u64 b, u64 neg1) {
    u64 r; asm("fma.rn.f32x2 %0,%1,%2,%3;" : "=l"(r) : "l"(b), "l"(neg1), "l"(a)); return r;
}
// bank-conflict-avoiding swizzle: logical (block n, col c) -> physical col
__device__ __forceinline__ int swz(int n, int c) {
    return n * 64 + (c ^ ((n & 7) << 3));
}

// ---------------- prepass: C = (B @ H64) / 64 ----------------
__global__ void prep_kernel(const float* __restrict__ innerB) {
    const int t = blockIdx.x * blockDim.x + threadIdx.x;   // row of a 64x64 block
    const float4* src = reinterpret_cast<const float4*>(innerB + (size_t)t * 64);
    float v[64];
    #pragma unroll
    for (int k = 0; k < 16; k++) {
        float4 f = src[k];
        v[4*k] = f.x; v[4*k+1] = f.y; v[4*k+2] = f.z; v[4*k+3] = f.w;
    }
    #pragma unroll
    for (int h = 1; h < 64; h <<= 1)
        #pragma unroll
        for (int m = 0; m < 64; m += 2*h)
            #pragma unroll
            for (int k = 0; k < h; k++) {
                float a = v[m+k], b = v[m+k+h];
                v[m+k] = a + b; v[m+k+h] = a - b;
            }
    float4* dst = reinterpret_cast<float4*>(g_C + (size_t)t * 64);
    const float s = 1.0f / 64.0f;
    #pragma unroll
    for (int k = 0; k < 16; k++)
        dst[k] = make_float4(v[4*k]*s, v[4*k+1]*s, v[4*k+2]*s, v[4*k+3]*s);
}

// ---------------- main fused kernel ----------------
__global__ __launch_bounds__(THREADS, 1)
void bh_fused_kernel(const float* __restrict__ x,
                     const float* __restrict__ finalB,
                     float* __restrict__ out)
{
    extern __shared__ float sd[];   // ROWS * D floats, swizzled layout
    const int tid = threadIdx.x;
    const size_t row0 = (size_t)blockIdx.x * ROWS;
    const u64 NEG1 = pack2(-1.0f);

    // ---- load ROWS rows (coalesced gmem read, swizzled smem store) ----
    {
        const float4* gx = reinterpret_cast<const float4*>(x + row0 * D);
        float4* s4 = reinterpret_cast<float4*>(sd);
        #pragma unroll
        for (int k = 0; k < (ROWS * D / 4) / THREADS; k++) {
            const int f   = tid + k * THREADS;
            const int r   = f >> 10;
            const int cq  = f & 1023;
            const int n   = cq >> 4;
            const int c   = (cq & 15) * 4;
            s4[r * 1024 + (swz(n, c) >> 2)] = gx[f];
        }
    }
    __syncthreads();

    const int g  = tid >> 3;         // group 0..63 (8 threads per group)
    const int ob = (tid & 7) * 8;    // output-col base within group
    const int pb = swz(g, ob);       // physical col base for writes (8-aligned)

    // FWHT mapping: thread -> (row hr, column-pair c0, half h2)
    const int lane = tid & 31;
    const int hr   = tid >> 6;                       // row 0..7
    const int wr   = (tid >> 5) & 1;                 // warp-in-row
    const int h2   = lane >> 4;                      // which 32-block half of m
    const int c0   = (wr * 16 + (lane & 15)) * 2;    // column pair base
    const int mb   = h2 * 32;

    #pragma unroll 1
    for (int stage = 0; stage < 2; stage++) {
        // ---- block-diag 64x64 matmul with C (inner H64 + scale folded) ----
        const float* C = g_C + ((size_t)stage * 64 + g) * 64 * 64;

        u64 acc[ROWS][4];
        #pragma unroll
        for (int r = 0; r < ROWS; r++)
            #pragma unroll
            for (int p = 0; p < 4; p++)
                acc[r][p] = 0ull;

        #pragma unroll 1
        for (int j = 0; j < 64; j += 4) {
            // hoist the whole block's C (8 LDG.128 back-to-back, MLP=8)
            ulonglong2 c0v[4], c1v[4];
            #pragma unroll
            for (int jj = 0; jj < 4; jj++) {
                c0v[jj] = *reinterpret_cast<const ulonglong2*>(&C[(j + jj) * 64 + ob]);
                c1v[jj] = *reinterpret_cast<const ulonglong2*>(&C[(j + jj) * 64 + ob + 4]);
            }
            const int pj = swz(g, j);
            #pragma unroll
            for (int r = 0; r < ROWS; r++) {
                const float4 xv = *reinterpret_cast<const float4*>(&sd[r * D + pj]);
                u64 xs;
                xs = pack2(xv.x);
                fma2(acc[r][0], xs, c0v[0].x); fma2(acc[r][1], xs, c0v[0].y);
                fma2(acc[r][2], xs, c1v[0].x); fma2(acc[r][3], xs, c1v[0].y);
                xs = pack2(xv.y);
                fma2(acc[r][0], xs, c0v[1].x); fma2(acc[r][1], xs, c0v[1].y);
                fma2(acc[r][2], xs, c1v[1].x); fma2(acc[r][3], xs, c1v[1].y);
                xs = pack2(xv.z);
                fma2(acc[r][0], xs, c0v[2].x); fma2(acc[r][1], xs, c0v[2].y);
                fma2(acc[r][2], xs, c1v[2].x); fma2(acc[r][3], xs, c1v[2].y);
                xs = pack2(xv.w);
                fma2(acc[r][0], xs, c0v[3].x); fma2(acc[r][1], xs, c0v[3].y);
                fma2(acc[r][2], xs, c1v[3].x); fma2(acc[r][3], xs, c1v[3].y);
            }
        }
        __syncthreads();   // all reads of the stage input done before overwrite
        #pragma unroll
        for (int r = 0; r < ROWS; r++) {
            ulonglong2* sp = reinterpret_cast<ulonglong2*>(&sd[r * D + pb]);
            sp[0] = make_ulonglong2(acc[r][0], acc[r][1]);
            sp[1] = make_ulonglong2(acc[r][2], acc[r][3]);
        }
        __syncthreads();

        // ---- outer H64: packed f32x2 over column pairs, 32 m per thread,
        //      top (h=32) level via shfl across warp halves ----
        {
            u64 v[32];
            #pragma unroll
            for (int m = 0; m < 32; m++) {
                const int n = mb + m;
                v[m] = *reinterpret_cast<const u64*>(
                    &sd[hr * D + n * 64 + (c0 ^ ((n & 7) << 3))]);
            }
            #pragma unroll
            for (int h = 1; h < 32; h <<= 1)
                #pragma unroll
                for (int m0 = 0; m0 < 32; m0 += 2 * h)
                    #pragma unroll
                    for (int k = 0; k < h; k++) {
                        const u64 a = v[m0 + k], b = v[m0 + k + h];
                        v[m0 + k]     = add2(a, b);
                        v[m0 + k + h] = sub2(a, b, NEG1);
                    }
            #pragma unroll
            for (int m = 0; m < 32; m++) {
                const u64 p = __shfl_xor_sync(0xffffffffu, v[m], 16);
                v[m] = h2 ? sub2(p, v[m], NEG1) : add2(v[m], p);
            }
            #pragma unroll
            for (int m = 0; m < 32; m++) {
                const int n = mb + m;
                *reinterpret_cast<u64*>(
                    &sd[hr * D + n * 64 + (c0 ^ ((n & 7) << 3))]) = v[m];
            }
        }
        __syncthreads();
    }

    // ---------------- final block-diag 128 x (32x32) matmul -> GMEM ----------------
    {
        const int rect = tid >> 2;        // 0..127 (4 threads per rect)
        const int ob2  = (tid & 3) * 8;
        const int n    = rect >> 1;
        const int cb   = (rect & 1) * 32;
        const float* B = finalB + (size_t)rect * 32 * 32;

        u64 acc[ROWS][4];
        #pragma unroll
        for (int r = 0; r < ROWS; r++)
            #pragma unroll
            for (int p = 0; p < 4; p++)
                acc[r][p] = 0ull;

        #pragma unroll 1
        for (int j = 0; j < 32; j += 4) {
            ulonglong2 b0v[4], b1v[4];
            #pragma unroll
            for (int jj = 0; jj < 4; jj++) {
                b0v[jj] = *reinterpret_cast<const ulonglong2*>(&B[(j + jj) * 32 + ob2]);
                b1v[jj] = *reinterpret_cast<const ulonglong2*>(&B[(j + jj) * 32 + ob2 + 4]);
            }
            const int pj = swz(n, cb + j);
            #pragma unroll
            for (int r = 0; r < ROWS; r++) {
                const float4 xv = *reinterpret_cast<const float4*>(&sd[r * D + pj]);
                u64 xs;
                xs = pack2(xv.x);
                fma2(acc[r][0], xs, b0v[0].x); fma2(acc[r][1], xs, b0v[0].y);
                fma2(acc[r][2], xs, b1v[0].x); fma2(acc[r][3], xs, b1v[0].y);
                xs = pack2(xv.y);
                fma2(acc[r][0], xs, b0v[1].x); fma2(acc[r][1], xs, b0v[1].y);
                fma2(acc[r][2], xs, b1v[1].x); fma2(acc[r][3], xs, b1v[1].y);
                xs = pack2(xv.z);
                fma2(acc[r][0], xs, b0v[2].x); fma2(acc[r][1], xs, b0v[2].y);
                fma2(acc[r][2], xs, b1v[2].x); fma2(acc[r][3], xs, b1v[2].y);
                xs = pack2(xv.w);
                fma2(acc[r][0], xs, b0v[3].x); fma2(acc[r][1], xs, b0v[3].y);
                fma2(acc[r][2], xs, b1v[3].x); fma2(acc[r][3], xs, b1v[3].y);
            }
        }
        #pragma unroll
        for (int r = 0; r < ROWS; r++) {
            ulonglong2* op = reinterpret_cast<ulonglong2*>(out + (row0 + r) * D + rect * 32 + ob2);
            op[0] = make_ulonglong2(acc[r][0], acc[r][1]);
            op[1] = make_ulonglong2(acc[r][2], acc[r][3]);
        }
    }
}

extern "C" void kernel_launch(void* const* d_in, const int* in_sizes, int n_in,
                              void* d_out, int out_size) {
    const float* x  = (const float*)d_in[0];   // [4,4096,4096] f32
    const float* iB = (const float*)d_in[1];   // [2,64,64,64]  f32
    const float* fB = (const float*)d_in[2];   // [128,32,32]   f32
    float* out = (float*)d_out;                // [4,4096,4096] f32

    prep_kernel<<<64, 128>>>(iB);

    const int smem = ROWS * D * sizeof(float); // 131072 bytes
    cudaFuncSetAttribute(bh_fused_kernel,
                         cudaFuncAttributeMaxDynamicSharedMemorySize, smem);
    const int nrows = 4 * 4096;
    bh_fused_kernel<<<nrows / ROWS, THREADS, smem>>>(x, fB, out);
}